// round 14
// baseline (speedup 1.0000x reference)
#include <cuda_runtime.h>
#include <cuda_fp16.h>
#include <math.h>
#include <stdint.h>

#define L_ALLC 2048
#define L_TXTC 512
#define L_IMGC 1536
#define NH     24
#define DHC    128
#define DIMC   3072
#define QKVD   9216
#define MLPD   12288

// ---------------- scratch (device globals; no runtime allocation) ----------------
__device__ __half g_xmod [L_ALLC * DIMC];
__device__ __half g_qkv  [L_ALLC * QKVD];
__device__ __half g_q    [NH * L_ALLC * DHC];
__device__ __half g_k    [NH * L_ALLC * DHC];
__device__ __half g_vt   [NH * DHC * L_ALLC];
__device__ __half g_ocat [L_ALLC * DIMC];
__device__ float  g_attno[L_ALLC * DIMC];
__device__ float  g_xres [L_ALLC * DIMC];
__device__ __half g_mlpin[L_ALLC * DIMC];
__device__ __half g_hid  [L_ALLC * MLPD];
// fp16 weight mirrors (converted each launch)
__device__ __half g_hw_qkv_t[QKVD * DIMC];
__device__ __half g_hw_qkv_i[QKVD * DIMC];
__device__ __half g_hw_proj [DIMC * DIMC];
__device__ __half g_hw_w1t  [MLPD * DIMC];
__device__ __half g_hw_w1i  [MLPD * DIMC];
__device__ __half g_hw_w2t  [DIMC * MLPD];
__device__ __half g_hw_w2i  [DIMC * MLPD];

__device__ __forceinline__ float gelu_tanh(float x) {
    float x3 = x * x * x;
    return 0.5f * x * (1.0f + tanhf(0.7978845608028654f * (x + 0.044715f * x3)));
}

__device__ __forceinline__ void cp_async16(unsigned smem_addr, const void* gptr) {
    asm volatile("cp.async.cg.shared.global [%0], [%1], 16;\n"
                 :: "r"(smem_addr), "l"(gptr));
}
__device__ __forceinline__ void cp_commit() {
    asm volatile("cp.async.commit_group;\n");
}
__device__ __forceinline__ void cp_wait1() {
    asm volatile("cp.async.wait_group 1;\n");
}
__device__ __forceinline__ void cp_wait2() {
    asm volatile("cp.async.wait_group 2;\n");
}

__device__ __forceinline__ void ldsm_x4(unsigned& r0, unsigned& r1,
                                        unsigned& r2, unsigned& r3, unsigned addr) {
    asm volatile("ldmatrix.sync.aligned.m8n8.x4.shared.b16 {%0,%1,%2,%3}, [%4];"
                 : "=r"(r0), "=r"(r1), "=r"(r2), "=r"(r3) : "r"(addr));
}

#define MMA16816(acc, a0, a1, a2, a3, b0, b1)                                  \
    asm volatile(                                                              \
        "mma.sync.aligned.m16n8k16.row.col.f32.f16.f16.f32 "                   \
        "{%0,%1,%2,%3}, {%4,%5,%6,%7}, {%8,%9}, {%0,%1,%2,%3};"                \
        : "+f"((acc)[0]), "+f"((acc)[1]), "+f"((acc)[2]), "+f"((acc)[3])       \
        : "r"(a0), "r"(a1), "r"(a2), "r"(a3), "r"(b0), "r"(b1))

// ---------------- fp16 mma GEMM, 128x128 CTA tile, BK=64, 3-stage ring -----------
// 128 threads, 4 warps in 2x2, warp tile 64x64 (better MMA:LDSM issue ratio).
// Dual weight set: m-tiles < mSplit use B1/bias1, rest B2/bias2.
// cmode: 0 f32 out, 1 f32+gelu, 2 half out, 3 half+gelu,
//        4 final: out = res + gate*(acc+bias), img/txt row remap.
#define MAT_BYTES   (128 * 72 * 2)
#define STAGE_BYTES (2 * MAT_BYTES)
#define GSMEM_BYTES (3 * STAGE_BYTES)

__global__ __launch_bounds__(128, 2)
void gemm_f16_kernel(const __half* __restrict__ A, long lda,
                     const __half* __restrict__ B1, const __half* __restrict__ B2,
                     long ldb,
                     const float* __restrict__ bias1, const float* __restrict__ bias2,
                     int mSplit,
                     void* __restrict__ Cv, long ldc,
                     int M, int K, int cmode,
                     const float* __restrict__ res,
                     const float* __restrict__ gate1, const float* __restrict__ gate2)
{
    extern __shared__ float sm[];
    const unsigned sbase = (unsigned)__cvta_generic_to_shared(sm);

    const int tid = threadIdx.x;
    const int nm = M >> 7;
    const int bm = blockIdx.x % nm;     // M fastest
    const int bn = blockIdx.x / nm;

    const __half* Ag = A + (long)bm * 128 * lda;
    const __half* Bg = (bm < mSplit ? B1 : B2) + (long)bn * 128 * ldb;
    const float*  bias = (bm < mSplit) ? bias1 : bias2;
    const float*  gate = (bm < mSplit) ? gate1 : gate2;

    const int lane = tid & 31;
    const int warp = tid >> 5;
    const int wm = (warp >> 1) * 64;
    const int wn = (warp & 1) * 64;
    const int qr = lane >> 2;
    const int qc = lane & 3;

    // producer: 1024 16B-chunks per matrix / 128 threads = 8 per thread per matrix
    const int pc8 = (tid & 7) * 8;

    const unsigned a_off =
        (unsigned)(((wm + (lane & 7) + ((lane >> 3) & 1) * 8) * 72 + (lane >> 4) * 8) * 2);
    const unsigned b_off = MAT_BYTES +
        (unsigned)(((wn + (lane & 7) + (lane >> 4) * 8) * 72 + ((lane >> 3) & 1) * 8) * 2);

    float acc[4][8][4];
#pragma unroll
    for (int mi = 0; mi < 4; mi++)
#pragma unroll
        for (int ni = 0; ni < 8; ni++)
#pragma unroll
            for (int e = 0; e < 4; e++) acc[mi][ni][e] = 0.0f;

    const int T = K >> 6;

    #define LOAD_SLAB(so, k0)                                                    \
    do {                                                                         \
        unsigned _a = sbase + (so), _b = _a + MAT_BYTES;                         \
        _Pragma("unroll")                                                        \
        for (int r = 0; r < 8; r++) {                                            \
            int row = (tid + r * 128) >> 3;                                      \
            unsigned off = (unsigned)(row * 72 + pc8) * 2u;                      \
            cp_async16(_a + off, Ag + (long)row * lda + (k0) + pc8);             \
            cp_async16(_b + off, Bg + (long)row * ldb + (k0) + pc8);             \
        }                                                                        \
    } while (0)

    LOAD_SLAB(0, 0);
    cp_commit();
    LOAD_SLAB(STAGE_BYTES, 64);
    cp_commit();

    unsigned so_c = 0;
    unsigned so_l = 2 * STAGE_BYTES;
    for (int t = 0; t < T; t++) {
        if (t + 2 < T) LOAD_SLAB(so_l, (t + 2) << 6);
        cp_commit();
        cp_wait2();
        __syncthreads();

        const unsigned abase = sbase + so_c + a_off;
        const unsigned bbase = sbase + so_c + b_off;

#pragma unroll
        for (int ks = 0; ks < 64; ks += 16) {
            unsigned a[4][4], b[8][2];
#pragma unroll
            for (int mi = 0; mi < 4; mi++)
                ldsm_x4(a[mi][0], a[mi][1], a[mi][2], a[mi][3],
                        abase + (unsigned)((mi * 16 * 72 + ks) * 2));
#pragma unroll
            for (int p = 0; p < 4; p++)
                ldsm_x4(b[2 * p][0], b[2 * p][1], b[2 * p + 1][0], b[2 * p + 1][1],
                        bbase + (unsigned)((p * 16 * 72 + ks) * 2));
#pragma unroll
            for (int mi = 0; mi < 4; mi++)
#pragma unroll
                for (int ni = 0; ni < 8; ni++)
                    MMA16816(acc[mi][ni], a[mi][0], a[mi][1], a[mi][2], a[mi][3],
                             b[ni][0], b[ni][1]);
        }
        __syncthreads();

        so_c += STAGE_BYTES; if (so_c == GSMEM_BYTES) so_c = 0;
        so_l += STAGE_BYTES; if (so_l == GSMEM_BYTES) so_l = 0;
    }

    // ---- epilogue ----
#pragma unroll
    for (int ni = 0; ni < 8; ni++) {
        int col = wn + ni * 8 + qc * 2;
        float b0 = bias ? bias[(long)bn * 128 + col]     : 0.0f;
        float b1 = bias ? bias[(long)bn * 128 + col + 1] : 0.0f;
#pragma unroll
        for (int mi = 0; mi < 4; mi++) {
            int row = wm + mi * 16 + qr;
            float t0 = acc[mi][ni][0] + b0;
            float t1 = acc[mi][ni][1] + b1;
            float t2 = acc[mi][ni][2] + b0;
            float t3 = acc[mi][ni][3] + b1;
            if (cmode == 1 || cmode == 3) {
                t0 = gelu_tanh(t0); t1 = gelu_tanh(t1);
                t2 = gelu_tanh(t2); t3 = gelu_tanh(t3);
            }
            if (cmode == 4) {
                // out = res + gate*val, with img-first/txt-second row remap
                long gcol = (long)bn * 128 + col;
                float gv0 = gate[gcol], gv1 = gate[gcol + 1];
                int l0 = bm * 128 + row;
                int l1 = l0 + 8;
                const float* r0 = res + (long)l0 * ldc + gcol;
                const float* r1 = res + (long)l1 * ldc + gcol;
                long d0 = (l0 < L_TXTC) ? (long)(L_IMGC + l0) : (long)(l0 - L_TXTC);
                long d1 = (l1 < L_TXTC) ? (long)(L_IMGC + l1) : (long)(l1 - L_TXTC);
                float* Cf = (float*)Cv;
                *(float2*)(Cf + d0 * ldc + gcol) =
                    make_float2(r0[0] + gv0 * t0, r0[1] + gv1 * t1);
                *(float2*)(Cf + d1 * ldc + gcol) =
                    make_float2(r1[0] + gv0 * t2, r1[1] + gv1 * t3);
            } else if (cmode < 2) {
                float* Cf = (float*)Cv + (long)bm * 128 * ldc + (long)bn * 128;
                *(float2*)(Cf + (long)row * ldc + col)       = make_float2(t0, t1);
                *(float2*)(Cf + (long)(row + 8) * ldc + col) = make_float2(t2, t3);
            } else {
                __half* Ch = (__half*)Cv + (long)bm * 128 * ldc + (long)bn * 128;
                *(__half2*)(Ch + (long)row * ldc + col)       = __floats2half2_rn(t0, t1);
                *(__half2*)(Ch + (long)(row + 8) * ldc + col) = __floats2half2_rn(t2, t3);
            }
        }
    }
    #undef LOAD_SLAB
}

// ---------------- fused flash attention ------------------------------------------
#define FA_QB 34816u                        // 128*136*2
#define FA_SMEM (5 * FA_QB)                 // 174080

__global__ __launch_bounds__(256, 1)
void flash_attn_kernel()
{
    extern __shared__ char fsm[];
    const unsigned sbase = (unsigned)__cvta_generic_to_shared(fsm);
    const int tid = threadIdx.x, lane = tid & 31, warp = tid >> 5;
    const int bm = blockIdx.x, h = blockIdx.y;

    const __half* Qg = g_q + ((long)h * L_ALLC + (long)bm * 128) * DHC;
    const __half* Kg = g_k + (long)h * L_ALLC * DHC;
    const __half* Vg = g_vt + (long)h * DHC * L_ALLC;   // [d][l]

    const unsigned sQ  = sbase;
    const unsigned sK0 = sbase + FA_QB,     sK1 = sK0 + FA_QB;
    const unsigned sV0 = sK1 + FA_QB,       sV1 = sV0 + FA_QB;

#pragma unroll
    for (int i = 0; i < 8; i++) {
        int c = tid + i * 256;
        int row = c >> 4, col = (c & 15) * 8;
        cp_async16(sQ + (unsigned)(row * 136 + col) * 2, Qg + (long)row * DHC + col);
    }
    cp_commit();

    #define FA_LOAD(sk, sv, t)                                                      \
    do {                                                                            \
        const __half* kp = Kg + (long)(t) * 128 * DHC;                              \
        const __half* vp = Vg + (t) * 128;                                          \
        _Pragma("unroll")                                                           \
        for (int i = 0; i < 8; i++) {                                               \
            int c = tid + i * 256;                                                  \
            int row = c >> 4, col = (c & 15) * 8;                                   \
            unsigned so = (unsigned)(row * 136 + col) * 2;                          \
            cp_async16((sk) + so, kp + (long)row * DHC + col);                      \
            cp_async16((sv) + so, vp + (long)row * L_ALLC + col);                   \
        }                                                                           \
    } while (0)

    FA_LOAD(sK0, sV0, 0);
    cp_commit();

    const int qr = lane >> 2, qc = lane & 3;
    const unsigned a_off =
        (unsigned)(((warp * 16 + (lane & 7) + ((lane >> 3) & 1) * 8) * 136 + (lane >> 4) * 8) * 2);
    const unsigned b_off =
        (unsigned)((((lane & 7) + (lane >> 4) * 8) * 136 + ((lane >> 3) & 1) * 8) * 2);

    float oacc[16][4];
#pragma unroll
    for (int n = 0; n < 16; n++)
#pragma unroll
        for (int e = 0; e < 4; e++) oacc[n][e] = 0.0f;
    float mrow[2] = { -1e30f, -1e30f };
    float lrow[2] = { 0.0f, 0.0f };

    const int NT = L_ALLC / 128;   // 16
    for (int t = 0; t < NT; t++) {
        if (t + 1 < NT) {
            if (t & 1) FA_LOAD(sK0, sV0, t + 1);
            else       FA_LOAD(sK1, sV1, t + 1);
        }
        cp_commit();
        cp_wait1();
        __syncthreads();

        const unsigned kb = (t & 1) ? sK1 : sK0;
        const unsigned vb = (t & 1) ? sV1 : sV0;

        float sacc[16][4];
#pragma unroll
        for (int n = 0; n < 16; n++)
#pragma unroll
            for (int e = 0; e < 4; e++) sacc[n][e] = 0.0f;

#pragma unroll
        for (int ks = 0; ks < 8; ks++) {
            unsigned a0, a1, a2, a3;
            ldsm_x4(a0, a1, a2, a3, sQ + a_off + (unsigned)(ks * 32));
#pragma unroll
            for (int nj = 0; nj < 8; nj++) {
                unsigned b0, b1, b2, b3;
                ldsm_x4(b0, b1, b2, b3,
                        kb + b_off + (unsigned)(nj * 16 * 136 * 2 + ks * 32));
                MMA16816(sacc[2 * nj],     a0, a1, a2, a3, b0, b1);
                MMA16816(sacc[2 * nj + 1], a0, a1, a2, a3, b2, b3);
            }
        }

#pragma unroll
        for (int g = 0; g < 2; g++) {
            float mx = -1e30f;
#pragma unroll
            for (int n = 0; n < 16; n++)
                mx = fmaxf(mx, fmaxf(sacc[n][2 * g], sacc[n][2 * g + 1]));
            mx = fmaxf(mx, __shfl_xor_sync(0xffffffffu, mx, 1));
            mx = fmaxf(mx, __shfl_xor_sync(0xffffffffu, mx, 2));
            float nm = fmaxf(mrow[g], mx);
            float sc = __expf(mrow[g] - nm);
            mrow[g] = nm;
            float rs = 0.0f;
#pragma unroll
            for (int n = 0; n < 16; n++) {
                float e0 = __expf(sacc[n][2 * g] - nm);
                float e1 = __expf(sacc[n][2 * g + 1] - nm);
                sacc[n][2 * g] = e0; sacc[n][2 * g + 1] = e1;
                rs += e0 + e1;
            }
            rs += __shfl_xor_sync(0xffffffffu, rs, 1);
            rs += __shfl_xor_sync(0xffffffffu, rs, 2);
            lrow[g] = lrow[g] * sc + rs;
#pragma unroll
            for (int n = 0; n < 16; n++) {
                oacc[n][2 * g]     *= sc;
                oacc[n][2 * g + 1] *= sc;
            }
        }

        unsigned p[16][2];
#pragma unroll
        for (int n = 0; n < 16; n++) {
            __half2 h0 = __floats2half2_rn(sacc[n][0], sacc[n][1]);
            __half2 h1 = __floats2half2_rn(sacc[n][2], sacc[n][3]);
            p[n][0] = *(unsigned*)&h0;
            p[n][1] = *(unsigned*)&h1;
        }

#pragma unroll
        for (int ks = 0; ks < 8; ks++) {
            unsigned a0 = p[2 * ks][0], a1 = p[2 * ks][1];
            unsigned a2 = p[2 * ks + 1][0], a3 = p[2 * ks + 1][1];
#pragma unroll
            for (int nj = 0; nj < 8; nj++) {
                unsigned b0, b1, b2, b3;
                ldsm_x4(b0, b1, b2, b3,
                        vb + b_off + (unsigned)(nj * 16 * 136 * 2 + ks * 32));
                MMA16816(oacc[2 * nj],     a0, a1, a2, a3, b0, b1);
                MMA16816(oacc[2 * nj + 1], a0, a1, a2, a3, b2, b3);
            }
        }
        __syncthreads();
    }

    float inv0 = 1.0f / lrow[0];
    float inv1 = 1.0f / lrow[1];
    __half* Og = g_ocat + (long)(bm * 128 + warp * 16) * DIMC + h * DHC;
#pragma unroll
    for (int n = 0; n < 16; n++) {
        int col = n * 8 + qc * 2;
        *(__half2*)(Og + (long)qr * DIMC + col) =
            __floats2half2_rn(oacc[n][0] * inv0, oacc[n][1] * inv0);
        *(__half2*)(Og + (long)(qr + 8) * DIMC + col) =
            __floats2half2_rn(oacc[n][2] * inv1, oacc[n][3] * inv1);
    }
    #undef FA_LOAD
}

// ---------------- fp32 -> fp16 convert -------------------------------------------
__global__ __launch_bounds__(256)
void f2h_kernel(const float* __restrict__ src, __half* __restrict__ dst, int n)
{
    int i = (blockIdx.x * 256 + threadIdx.x) * 4;
    if (i < n) {
        float4 v = *(const float4*)(src + i);
        *(__half2*)(dst + i)     = __floats2half2_rn(v.x, v.y);
        *(__half2*)(dst + i + 2) = __floats2half2_rn(v.z, v.w);
    }
}

// ---------------- LN + modulation -> fp16 xmod -----------------------------------
__global__ void ln_mod_kernel(const float* __restrict__ txt_emb,
                              const float* __restrict__ img_emb,
                              const float* __restrict__ tsc, const float* __restrict__ tsh,
                              const float* __restrict__ isc, const float* __restrict__ ish)
{
    int l = blockIdx.x, tid = threadIdx.x;
    __shared__ float row[DIMC];
    __shared__ float redA[8], redB[8];

    const float *x, *sc, *sh;
    if (l < L_TXTC) { x = txt_emb + (long)l * DIMC; sc = tsc; sh = tsh; }
    else            { x = img_emb + (long)(l - L_TXTC) * DIMC; sc = isc; sh = ish; }

    float s = 0.f, s2 = 0.f;
    for (int i = tid; i < DIMC; i += 256) {
        float v = x[i]; row[i] = v; s += v; s2 += v * v;
    }
#pragma unroll
    for (int o = 16; o > 0; o >>= 1) {
        s  += __shfl_xor_sync(0xffffffffu, s,  o);
        s2 += __shfl_xor_sync(0xffffffffu, s2, o);
    }
    int w = tid >> 5;
    if ((tid & 31) == 0) { redA[w] = s; redB[w] = s2; }
    __syncthreads();
    if (tid == 0) {
        float a = 0.f, b = 0.f;
        for (int i = 0; i < 8; i++) { a += redA[i]; b += redB[i]; }
        redA[0] = a; redB[0] = b;
    }
    __syncthreads();
    float mean = redA[0] / DIMC;
    float var  = redB[0] / DIMC - mean * mean;
    float rstd = rsqrtf(var + 1e-6f);

    __half* out = g_xmod + (long)l * DIMC;
    for (int i = tid; i < DIMC; i += 256)
        out[i] = __float2half((1.0f + sc[i]) * ((row[i] - mean) * rstd) + sh[i]);
}

// ---------------- QKV post: shuffle-based RMSNorm + RoPE + fp16 transpose ---------
__global__ void qkv_post_kernel(const float* __restrict__ pe,
                                const float* __restrict__ tqw,
                                const float* __restrict__ iqw)
{
    int l = blockIdx.x, h = blockIdx.y, d = threadIdx.x;
    int lane = d & 31, warp = d >> 5;
    const __half* base = g_qkv + (long)l * QKVD + h * DHC;
    float qv = __half2float(base[d]);
    float kv = __half2float(base[DIMC + d]);
    float vv = __half2float(base[2 * DIMC + d]);
    const float* w = (l < L_TXTC) ? tqw : iqw;

    float a = qv * qv, b = kv * kv;
#pragma unroll
    for (int o = 16; o > 0; o >>= 1) {
        a += __shfl_xor_sync(0xffffffffu, a, o);
        b += __shfl_xor_sync(0xffffffffu, b, o);
    }
    __shared__ float ra[4], rb[4];
    if (lane == 0) { ra[warp] = a; rb[warp] = b; }
    __syncthreads();
    a = ra[0] + ra[1] + ra[2] + ra[3];
    b = rb[0] + rb[1] + rb[2] + rb[3];
    float rq = rsqrtf(a / DHC + 1e-6f);
    float rk = rsqrtf(b / DHC + 1e-6f);

    float xq = qv * rq * w[d];
    float xk = kv * rk * w[d];
    float pq = __shfl_xor_sync(0xffffffffu, xq, 1);
    float pk = __shfl_xor_sync(0xffffffffu, xk, 1);

    int j = d >> 1;
    float c = pe[(long)l * 256 + j * 4];
    float s = pe[(long)l * 256 + j * 4 + 2];
    float qr, kr;
    if ((d & 1) == 0) {
        qr = xq * c - pq * s;
        kr = xk * c - pk * s;
    } else {
        qr = pq * s + xq * c;
        kr = pk * s + xk * c;
    }
    long qi = ((long)h * L_ALLC + l) * DHC + d;
    g_q[qi] = __float2half(qr * 0.08838834764831845f);  // DH^-0.5 folded into q
    g_k[qi] = __float2half(kr);
    g_vt[((long)h * DHC + d) * L_ALLC + l] = __float2half(vv);
}

// ---------------- residual + LN + MLP modulation (fp16 mlpin; xres saved) ---------
__global__ void res_ln_kernel(const float* __restrict__ txt_emb,
                              const float* __restrict__ img_emb,
                              const float* __restrict__ tgate, const float* __restrict__ igate,
                              const float* __restrict__ tmsc,  const float* __restrict__ tmsh,
                              const float* __restrict__ imsc,  const float* __restrict__ imsh)
{
    int l = blockIdx.x, tid = threadIdx.x;
    __shared__ float row[DIMC];
    __shared__ float redA[8], redB[8];

    const float *emb, *gate, *msc, *msh;
    if (l < L_TXTC) { emb = txt_emb + (long)l * DIMC; gate = tgate; msc = tmsc; msh = tmsh; }
    else            { emb = img_emb + (long)(l - L_TXTC) * DIMC; gate = igate; msc = imsc; msh = imsh; }

    const float* attn = g_attno + (long)l * DIMC;
    float* xres = g_xres + (long)l * DIMC;

    float s = 0.f, s2 = 0.f;
    for (int i = tid; i < DIMC; i += 256) {
        float v = emb[i] + gate[i] * attn[i];
        row[i] = v; xres[i] = v; s += v; s2 += v * v;
    }
#pragma unroll
    for (int o = 16; o > 0; o >>= 1) {
        s  += __shfl_xor_sync(0xffffffffu, s,  o);
        s2 += __shfl_xor_sync(0xffffffffu, s2, o);
    }
    int w = tid >> 5;
    if ((tid & 31) == 0) { redA[w] = s; redB[w] = s2; }
    __syncthreads();
    if (tid == 0) {
        float a = 0.f, b = 0.f;
        for (int i = 0; i < 8; i++) { a += redA[i]; b += redB[i]; }
        redA[0] = a; redB[0] = b;
    }
    __syncthreads();
    float mean = redA[0] / DIMC;
    float var  = redB[0] / DIMC - mean * mean;
    float rstd = rsqrtf(var + 1e-6f);

    __half* out = g_mlpin + (long)l * DIMC;
    for (int i = tid; i < DIMC; i += 256)
        out[i] = __float2half((1.0f + msc[i]) * ((row[i] - mean) * rstd) + msh[i]);
}

// ---------------- host ----------------------------------------------------------
static void hgemm(const __half* A, long lda,
                  const __half* B1, const __half* B2, long ldb,
                  const float* bias1, const float* bias2, int mSplit,
                  void* C, long ldc, int M, int N, int K, int cmode,
                  const float* res = nullptr,
                  const float* gate1 = nullptr, const float* gate2 = nullptr)
{
    dim3 grid((M / 128) * (N / 128), 1, 1);
    gemm_f16_kernel<<<grid, 128, GSMEM_BYTES>>>(A, lda, B1, B2, ldb,
                                                bias1, bias2, mSplit,
                                                C, ldc, M, K, cmode,
                                                res, gate1, gate2);
}

static void f2h(const float* src, __half* dst, long n)
{
    f2h_kernel<<<(unsigned)((n / 4 + 255) / 256), 256>>>(src, dst, (int)n);
}

extern "C" void kernel_launch(void* const* d_in, const int* in_sizes, int n_in,
                              void* d_out, int out_size)
{
    cudaFuncSetAttribute(gemm_f16_kernel,
                         cudaFuncAttributeMaxDynamicSharedMemorySize, GSMEM_BYTES);
    cudaFuncSetAttribute(flash_attn_kernel,
                         cudaFuncAttributeMaxDynamicSharedMemorySize, FA_SMEM);

    const float* img_emb = (const float*)d_in[0];
    const float* txt_emb = (const float*)d_in[1];
    const float* pe      = (const float*)d_in[2];
    const float* i_asc = (const float*)d_in[3];
    const float* i_ash = (const float*)d_in[4];
    const float* i_ag  = (const float*)d_in[5];
    const float* i_msc = (const float*)d_in[6];
    const float* i_msh = (const float*)d_in[7];
    const float* i_mg  = (const float*)d_in[8];
    const float* t_asc = (const float*)d_in[9];
    const float* t_ash = (const float*)d_in[10];
    const float* t_ag  = (const float*)d_in[11];
    const float* t_msc = (const float*)d_in[12];
    const float* t_msh = (const float*)d_in[13];
    const float* t_mg  = (const float*)d_in[14];
    const float* i_qkv_w = (const float*)d_in[15];
    const float* i_qkv_b = (const float*)d_in[16];
    const float* i_qnw   = (const float*)d_in[17];
    const float* t_qkv_w = (const float*)d_in[18];
    const float* t_qkv_b = (const float*)d_in[19];
    const float* t_qnw   = (const float*)d_in[20];
    const float* proj_w  = (const float*)d_in[21];
    const float* proj_b  = (const float*)d_in[22];
    const float* i_w1 = (const float*)d_in[23];
    const float* i_b1 = (const float*)d_in[24];
    const float* i_w2 = (const float*)d_in[25];
    const float* i_b2 = (const float*)d_in[26];
    const float* t_w1 = (const float*)d_in[27];
    const float* t_b1 = (const float*)d_in[28];
    const float* t_w2 = (const float*)d_in[29];
    const float* t_b2 = (const float*)d_in[30];
    // d_in[31] = mask: all-true in this problem -> no-op in attention.

    float *p_attno, *p_xres;
    __half *p_xmod, *p_qkv, *p_ocat, *p_mlpin, *p_hid;
    __half *w_qkv_t, *w_qkv_i, *w_proj, *w_w1t, *w_w1i, *w_w2t, *w_w2i;
    cudaGetSymbolAddress((void**)&p_xmod,  g_xmod);
    cudaGetSymbolAddress((void**)&p_qkv,   g_qkv);
    cudaGetSymbolAddress((void**)&p_ocat,  g_ocat);
    cudaGetSymbolAddress((void**)&p_attno, g_attno);
    cudaGetSymbolAddress((void**)&p_xres,  g_xres);
    cudaGetSymbolAddress((void**)&p_mlpin, g_mlpin);
    cudaGetSymbolAddress((void**)&p_hid,   g_hid);
    cudaGetSymbolAddress((void**)&w_qkv_t, g_hw_qkv_t);
    cudaGetSymbolAddress((void**)&w_qkv_i, g_hw_qkv_i);
    cudaGetSymbolAddress((void**)&w_proj,  g_hw_proj);
    cudaGetSymbolAddress((void**)&w_w1t,   g_hw_w1t);
    cudaGetSymbolAddress((void**)&w_w1i,   g_hw_w1i);
    cudaGetSymbolAddress((void**)&w_w2t,   g_hw_w2t);
    cudaGetSymbolAddress((void**)&w_w2i,   g_hw_w2i);

    float* out = (float*)d_out;

    // 0. convert weights to fp16
    f2h(t_qkv_w, w_qkv_t, (long)QKVD * DIMC);
    f2h(i_qkv_w, w_qkv_i, (long)QKVD * DIMC);
    f2h(proj_w,  w_proj,  (long)DIMC * DIMC);
    f2h(t_w1,    w_w1t,   (long)MLPD * DIMC);
    f2h(i_w1,    w_w1i,   (long)MLPD * DIMC);
    f2h(t_w2,    w_w2t,   (long)DIMC * MLPD);
    f2h(i_w2,    w_w2i,   (long)DIMC * MLPD);

    // 1. LN + attn modulation -> fp16 xmod (txt rows first, then img)
    ln_mod_kernel<<<L_ALLC, 256>>>(txt_emb, img_emb, t_asc, t_ash, i_asc, i_ash);

    // 2. fused QKV GEMM (txt m-tiles 0-3, img m-tiles 4-15)
    hgemm(p_xmod, DIMC, w_qkv_t, w_qkv_i, DIMC, t_qkv_b, i_qkv_b, L_TXTC / 128,
          p_qkv, QKVD, L_ALLC, QKVD, DIMC, 2);

    // 3. RMSNorm + RoPE + scale + fp16 layout
    {
        dim3 grid(L_ALLC, NH);
        qkv_post_kernel<<<grid, DHC>>>(pe, t_qnw, i_qnw);
    }

    // 4. fused flash attention -> fp16 ocat
    {
        dim3 grid(L_ALLC / 128, NH);
        flash_attn_kernel<<<grid, 256, FA_SMEM>>>();
    }

    // 5. shared proj (fp32 out)
    hgemm(p_ocat, DIMC, w_proj, w_proj, DIMC, proj_b, proj_b, L_ALLC / 128,
          p_attno, DIMC, L_ALLC, DIMC, DIMC, 0);

    // 6. residual + LN + mlp modulation -> fp16 mlpin (+ xres)
    res_ln_kernel<<<L_ALLC, 256>>>(txt_emb, img_emb, t_ag, i_ag, t_msc, t_msh, i_msc, i_msh);

    // 7. fused MLP up + GELU -> fp16 hid
    hgemm(p_mlpin, DIMC, w_w1t, w_w1i, DIMC, t_b1, i_b1, L_TXTC / 128,
          p_hid, MLPD, L_ALLC, MLPD, DIMC, 3);

    // 8. fused MLP down + gate + residual + output remap (img first, then txt)
    hgemm(p_hid, MLPD, w_w2t, w_w2i, MLPD, t_b2, i_b2, L_TXTC / 128,
          out, DIMC, L_ALLC, DIMC, MLPD, 4, p_xres, t_mg, i_mg);
}

// round 15
// speedup vs baseline: 1.0749x; 1.0749x over previous
#include <cuda_runtime.h>
#include <cuda_fp16.h>
#include <math.h>
#include <stdint.h>

#define L_ALLC 2048
#define L_TXTC 512
#define L_IMGC 1536
#define NH     24
#define DHC    128
#define DIMC   3072
#define QKVD   9216
#define MLPD   12288

// ---------------- scratch (device globals; no runtime allocation) ----------------
__device__ __half g_xmod [L_ALLC * DIMC];
__device__ __half g_qkv  [L_ALLC * QKVD];
__device__ __half g_q    [NH * L_ALLC * DHC];
__device__ __half g_k    [NH * L_ALLC * DHC];
__device__ __half g_vt   [NH * DHC * L_ALLC];
__device__ __half g_ocat [L_ALLC * DIMC];
__device__ float  g_attno[L_ALLC * DIMC];
__device__ float  g_xres [L_ALLC * DIMC];
__device__ __half g_mlpin[L_ALLC * DIMC];
__device__ __half g_hid  [L_ALLC * MLPD];
// fp16 weight mirrors (converted each launch)
__device__ __half g_hw_qkv_t[QKVD * DIMC];
__device__ __half g_hw_qkv_i[QKVD * DIMC];
__device__ __half g_hw_proj [DIMC * DIMC];
__device__ __half g_hw_w1t  [MLPD * DIMC];
__device__ __half g_hw_w1i  [MLPD * DIMC];
__device__ __half g_hw_w2t  [DIMC * MLPD];
__device__ __half g_hw_w2i  [DIMC * MLPD];

__device__ __forceinline__ float gelu_tanh(float x) {
    float x3 = x * x * x;
    return 0.5f * x * (1.0f + tanhf(0.7978845608028654f * (x + 0.044715f * x3)));
}

__device__ __forceinline__ void cp_async16(unsigned smem_addr, const void* gptr) {
    asm volatile("cp.async.cg.shared.global [%0], [%1], 16;\n"
                 :: "r"(smem_addr), "l"(gptr));
}
__device__ __forceinline__ void cp_commit() {
    asm volatile("cp.async.commit_group;\n");
}
__device__ __forceinline__ void cp_wait1() {
    asm volatile("cp.async.wait_group 1;\n");
}
__device__ __forceinline__ void cp_wait2() {
    asm volatile("cp.async.wait_group 2;\n");
}

__device__ __forceinline__ void ldsm_x4(unsigned& r0, unsigned& r1,
                                        unsigned& r2, unsigned& r3, unsigned addr) {
    asm volatile("ldmatrix.sync.aligned.m8n8.x4.shared.b16 {%0,%1,%2,%3}, [%4];"
                 : "=r"(r0), "=r"(r1), "=r"(r2), "=r"(r3) : "r"(addr));
}

#define MMA16816(acc, a0, a1, a2, a3, b0, b1)                                  \
    asm volatile(                                                              \
        "mma.sync.aligned.m16n8k16.row.col.f32.f16.f16.f32 "                   \
        "{%0,%1,%2,%3}, {%4,%5,%6,%7}, {%8,%9}, {%0,%1,%2,%3};"                \
        : "+f"((acc)[0]), "+f"((acc)[1]), "+f"((acc)[2]), "+f"((acc)[3])       \
        : "r"(a0), "r"(a1), "r"(a2), "r"(a3), "r"(b0), "r"(b1))

// ---------------- fp16 mma GEMM, 128x128 CTA tile, BK=64, 3-stage ring -----------
// 256 threads, 8 warps in 2x4, warp tile 64x32 (round-13 proven config).
// Dual weight set: m-tiles < mSplit use B1/bias1, rest B2/bias2.
// cmode: 0 f32 out, 1 f32+gelu, 2 half out, 3 half+gelu,
//        4 final: out = res + gate*(acc+bias), img-first/txt-second row remap.
#define MAT_BYTES   (128 * 72 * 2)
#define STAGE_BYTES (2 * MAT_BYTES)
#define GSMEM_BYTES (3 * STAGE_BYTES)

__global__ __launch_bounds__(256, 2)
void gemm_f16_kernel(const __half* __restrict__ A, long lda,
                     const __half* __restrict__ B1, const __half* __restrict__ B2,
                     long ldb,
                     const float* __restrict__ bias1, const float* __restrict__ bias2,
                     int mSplit,
                     void* __restrict__ Cv, long ldc,
                     int M, int K, int cmode,
                     const float* __restrict__ res,
                     const float* __restrict__ gate1, const float* __restrict__ gate2)
{
    extern __shared__ float sm[];
    const unsigned sbase = (unsigned)__cvta_generic_to_shared(sm);

    const int tid = threadIdx.x;
    const int nm = M >> 7;
    const int bm = blockIdx.x % nm;     // M fastest
    const int bn = blockIdx.x / nm;

    const __half* Ag = A + (long)bm * 128 * lda;
    const __half* Bg = (bm < mSplit ? B1 : B2) + (long)bn * 128 * ldb;
    const float*  bias = (bm < mSplit) ? bias1 : bias2;
    const float*  gate = (bm < mSplit) ? gate1 : gate2;

    const int lane = tid & 31;
    const int warp = tid >> 5;
    const int wm = (warp >> 2) * 64;
    const int wn = (warp & 3) * 32;
    const int qr = lane >> 2;
    const int qc = lane & 3;

    const int prow[4] = { (tid + 0) >> 3, (tid + 256) >> 3, (tid + 512) >> 3, (tid + 768) >> 3 };
    const int pc8 = (tid & 7) * 8;
    const unsigned poff[4] = {
        (unsigned)(prow[0] * 72 + pc8) * 2u, (unsigned)(prow[1] * 72 + pc8) * 2u,
        (unsigned)(prow[2] * 72 + pc8) * 2u, (unsigned)(prow[3] * 72 + pc8) * 2u };

    const unsigned a_off =
        (unsigned)(((wm + (lane & 7) + ((lane >> 3) & 1) * 8) * 72 + (lane >> 4) * 8) * 2);
    const unsigned b_off = MAT_BYTES +
        (unsigned)(((wn + (lane & 7) + (lane >> 4) * 8) * 72 + ((lane >> 3) & 1) * 8) * 2);

    float acc[4][4][4];
#pragma unroll
    for (int mi = 0; mi < 4; mi++)
#pragma unroll
        for (int ni = 0; ni < 4; ni++)
#pragma unroll
            for (int e = 0; e < 4; e++) acc[mi][ni][e] = 0.0f;

    const int T = K >> 6;

    #define LOAD_SLAB(so, k0)                                                    \
    do {                                                                         \
        unsigned _a = sbase + (so), _b = _a + MAT_BYTES;                         \
        _Pragma("unroll")                                                        \
        for (int r = 0; r < 4; r++) {                                            \
            cp_async16(_a + poff[r], Ag + (long)prow[r] * lda + (k0) + pc8);     \
            cp_async16(_b + poff[r], Bg + (long)prow[r] * ldb + (k0) + pc8);     \
        }                                                                        \
    } while (0)

    LOAD_SLAB(0, 0);
    cp_commit();
    LOAD_SLAB(STAGE_BYTES, 64);
    cp_commit();

    unsigned so_c = 0;
    unsigned so_l = 2 * STAGE_BYTES;
    for (int t = 0; t < T; t++) {
        if (t + 2 < T) LOAD_SLAB(so_l, (t + 2) << 6);
        cp_commit();
        cp_wait2();
        __syncthreads();

        const unsigned abase = sbase + so_c + a_off;
        const unsigned bbase = sbase + so_c + b_off;

#pragma unroll
        for (int ks = 0; ks < 64; ks += 16) {
            unsigned a[4][4], b[4][2];
#pragma unroll
            for (int mi = 0; mi < 4; mi++)
                ldsm_x4(a[mi][0], a[mi][1], a[mi][2], a[mi][3],
                        abase + (unsigned)((mi * 16 * 72 + ks) * 2));
            ldsm_x4(b[0][0], b[0][1], b[1][0], b[1][1],
                    bbase + (unsigned)(ks * 2));
            ldsm_x4(b[2][0], b[2][1], b[3][0], b[3][1],
                    bbase + (unsigned)((16 * 72 + ks) * 2));
#pragma unroll
            for (int mi = 0; mi < 4; mi++)
#pragma unroll
                for (int ni = 0; ni < 4; ni++)
                    MMA16816(acc[mi][ni], a[mi][0], a[mi][1], a[mi][2], a[mi][3],
                             b[ni][0], b[ni][1]);
        }
        __syncthreads();

        so_c += STAGE_BYTES; if (so_c == GSMEM_BYTES) so_c = 0;
        so_l += STAGE_BYTES; if (so_l == GSMEM_BYTES) so_l = 0;
    }

    // ---- epilogue ----
#pragma unroll
    for (int ni = 0; ni < 4; ni++) {
        int col = wn + ni * 8 + qc * 2;
        float b0 = bias ? bias[(long)bn * 128 + col]     : 0.0f;
        float b1 = bias ? bias[(long)bn * 128 + col + 1] : 0.0f;
#pragma unroll
        for (int mi = 0; mi < 4; mi++) {
            int row = wm + mi * 16 + qr;
            float t0 = acc[mi][ni][0] + b0;
            float t1 = acc[mi][ni][1] + b1;
            float t2 = acc[mi][ni][2] + b0;
            float t3 = acc[mi][ni][3] + b1;
            if (cmode == 1 || cmode == 3) {
                t0 = gelu_tanh(t0); t1 = gelu_tanh(t1);
                t2 = gelu_tanh(t2); t3 = gelu_tanh(t3);
            }
            if (cmode == 4) {
                // out = res + gate*val, img-first/txt-second row remap
                long gcol = (long)bn * 128 + col;
                float gv0 = gate[gcol], gv1 = gate[gcol + 1];
                int l0 = bm * 128 + row;
                int l1 = l0 + 8;
                const float* r0 = res + (long)l0 * ldc + gcol;
                const float* r1 = res + (long)l1 * ldc + gcol;
                long d0 = (l0 < L_TXTC) ? (long)(L_IMGC + l0) : (long)(l0 - L_TXTC);
                long d1 = (l1 < L_TXTC) ? (long)(L_IMGC + l1) : (long)(l1 - L_TXTC);
                float* Cf = (float*)Cv;
                *(float2*)(Cf + d0 * ldc + gcol) =
                    make_float2(r0[0] + gv0 * t0, r0[1] + gv1 * t1);
                *(float2*)(Cf + d1 * ldc + gcol) =
                    make_float2(r1[0] + gv0 * t2, r1[1] + gv1 * t3);
            } else if (cmode < 2) {
                float* Cf = (float*)Cv + (long)bm * 128 * ldc + (long)bn * 128;
                *(float2*)(Cf + (long)row * ldc + col)       = make_float2(t0, t1);
                *(float2*)(Cf + (long)(row + 8) * ldc + col) = make_float2(t2, t3);
            } else {
                __half* Ch = (__half*)Cv + (long)bm * 128 * ldc + (long)bn * 128;
                *(__half2*)(Ch + (long)row * ldc + col)       = __floats2half2_rn(t0, t1);
                *(__half2*)(Ch + (long)(row + 8) * ldc + col) = __floats2half2_rn(t2, t3);
            }
        }
    }
    #undef LOAD_SLAB
}

// ---------------- fused flash attention ------------------------------------------
#define FA_QB 34816u                        // 128*136*2
#define FA_SMEM (5 * FA_QB)                 // 174080

__global__ __launch_bounds__(256, 1)
void flash_attn_kernel()
{
    extern __shared__ char fsm[];
    const unsigned sbase = (unsigned)__cvta_generic_to_shared(fsm);
    const int tid = threadIdx.x, lane = tid & 31, warp = tid >> 5;
    const int bm = blockIdx.x, h = blockIdx.y;

    const __half* Qg = g_q + ((long)h * L_ALLC + (long)bm * 128) * DHC;
    const __half* Kg = g_k + (long)h * L_ALLC * DHC;
    const __half* Vg = g_vt + (long)h * DHC * L_ALLC;   // [d][l]

    const unsigned sQ  = sbase;
    const unsigned sK0 = sbase + FA_QB,     sK1 = sK0 + FA_QB;
    const unsigned sV0 = sK1 + FA_QB,       sV1 = sV0 + FA_QB;

#pragma unroll
    for (int i = 0; i < 8; i++) {
        int c = tid + i * 256;
        int row = c >> 4, col = (c & 15) * 8;
        cp_async16(sQ + (unsigned)(row * 136 + col) * 2, Qg + (long)row * DHC + col);
    }
    cp_commit();

    #define FA_LOAD(sk, sv, t)                                                      \
    do {                                                                            \
        const __half* kp = Kg + (long)(t) * 128 * DHC;                              \
        const __half* vp = Vg + (t) * 128;                                          \
        _Pragma("unroll")                                                           \
        for (int i = 0; i < 8; i++) {                                               \
            int c = tid + i * 256;                                                  \
            int row = c >> 4, col = (c & 15) * 8;                                   \
            unsigned so = (unsigned)(row * 136 + col) * 2;                          \
            cp_async16((sk) + so, kp + (long)row * DHC + col);                      \
            cp_async16((sv) + so, vp + (long)row * L_ALLC + col);                   \
        }                                                                           \
    } while (0)

    FA_LOAD(sK0, sV0, 0);
    cp_commit();

    const int qr = lane >> 2, qc = lane & 3;
    const unsigned a_off =
        (unsigned)(((warp * 16 + (lane & 7) + ((lane >> 3) & 1) * 8) * 136 + (lane >> 4) * 8) * 2);
    const unsigned b_off =
        (unsigned)((((lane & 7) + (lane >> 4) * 8) * 136 + ((lane >> 3) & 1) * 8) * 2);

    float oacc[16][4];
#pragma unroll
    for (int n = 0; n < 16; n++)
#pragma unroll
        for (int e = 0; e < 4; e++) oacc[n][e] = 0.0f;
    float mrow[2] = { -1e30f, -1e30f };
    float lrow[2] = { 0.0f, 0.0f };

    const int NT = L_ALLC / 128;   // 16
    for (int t = 0; t < NT; t++) {
        if (t + 1 < NT) {
            if (t & 1) FA_LOAD(sK0, sV0, t + 1);
            else       FA_LOAD(sK1, sV1, t + 1);
        }
        cp_commit();
        cp_wait1();
        __syncthreads();

        const unsigned kb = (t & 1) ? sK1 : sK0;
        const unsigned vb = (t & 1) ? sV1 : sV0;

        float sacc[16][4];
#pragma unroll
        for (int n = 0; n < 16; n++)
#pragma unroll
            for (int e = 0; e < 4; e++) sacc[n][e] = 0.0f;

#pragma unroll
        for (int ks = 0; ks < 8; ks++) {
            unsigned a0, a1, a2, a3;
            ldsm_x4(a0, a1, a2, a3, sQ + a_off + (unsigned)(ks * 32));
#pragma unroll
            for (int nj = 0; nj < 8; nj++) {
                unsigned b0, b1, b2, b3;
                ldsm_x4(b0, b1, b2, b3,
                        kb + b_off + (unsigned)(nj * 16 * 136 * 2 + ks * 32));
                MMA16816(sacc[2 * nj],     a0, a1, a2, a3, b0, b1);
                MMA16816(sacc[2 * nj + 1], a0, a1, a2, a3, b2, b3);
            }
        }

#pragma unroll
        for (int g = 0; g < 2; g++) {
            float mx = -1e30f;
#pragma unroll
            for (int n = 0; n < 16; n++)
                mx = fmaxf(mx, fmaxf(sacc[n][2 * g], sacc[n][2 * g + 1]));
            mx = fmaxf(mx, __shfl_xor_sync(0xffffffffu, mx, 1));
            mx = fmaxf(mx, __shfl_xor_sync(0xffffffffu, mx, 2));
            float nm = fmaxf(mrow[g], mx);
            float sc = __expf(mrow[g] - nm);
            mrow[g] = nm;
            float rs = 0.0f;
#pragma unroll
            for (int n = 0; n < 16; n++) {
                float e0 = __expf(sacc[n][2 * g] - nm);
                float e1 = __expf(sacc[n][2 * g + 1] - nm);
                sacc[n][2 * g] = e0; sacc[n][2 * g + 1] = e1;
                rs += e0 + e1;
            }
            rs += __shfl_xor_sync(0xffffffffu, rs, 1);
            rs += __shfl_xor_sync(0xffffffffu, rs, 2);
            lrow[g] = lrow[g] * sc + rs;
#pragma unroll
            for (int n = 0; n < 16; n++) {
                oacc[n][2 * g]     *= sc;
                oacc[n][2 * g + 1] *= sc;
            }
        }

        unsigned p[16][2];
#pragma unroll
        for (int n = 0; n < 16; n++) {
            __half2 h0 = __floats2half2_rn(sacc[n][0], sacc[n][1]);
            __half2 h1 = __floats2half2_rn(sacc[n][2], sacc[n][3]);
            p[n][0] = *(unsigned*)&h0;
            p[n][1] = *(unsigned*)&h1;
        }

#pragma unroll
        for (int ks = 0; ks < 8; ks++) {
            unsigned a0 = p[2 * ks][0], a1 = p[2 * ks][1];
            unsigned a2 = p[2 * ks + 1][0], a3 = p[2 * ks + 1][1];
#pragma unroll
            for (int nj = 0; nj < 8; nj++) {
                unsigned b0, b1, b2, b3;
                ldsm_x4(b0, b1, b2, b3,
                        vb + b_off + (unsigned)(nj * 16 * 136 * 2 + ks * 32));
                MMA16816(oacc[2 * nj],     a0, a1, a2, a3, b0, b1);
                MMA16816(oacc[2 * nj + 1], a0, a1, a2, a3, b2, b3);
            }
        }
        __syncthreads();
    }

    float inv0 = 1.0f / lrow[0];
    float inv1 = 1.0f / lrow[1];
    __half* Og = g_ocat + (long)(bm * 128 + warp * 16) * DIMC + h * DHC;
#pragma unroll
    for (int n = 0; n < 16; n++) {
        int col = n * 8 + qc * 2;
        *(__half2*)(Og + (long)qr * DIMC + col) =
            __floats2half2_rn(oacc[n][0] * inv0, oacc[n][1] * inv0);
        *(__half2*)(Og + (long)(qr + 8) * DIMC + col) =
            __floats2half2_rn(oacc[n][2] * inv1, oacc[n][3] * inv1);
    }
    #undef FA_LOAD
}

// ---------------- fp32 -> fp16 convert -------------------------------------------
__global__ __launch_bounds__(256)
void f2h_kernel(const float* __restrict__ src, __half* __restrict__ dst, int n)
{
    int i = (blockIdx.x * 256 + threadIdx.x) * 4;
    if (i < n) {
        float4 v = *(const float4*)(src + i);
        *(__half2*)(dst + i)     = __floats2half2_rn(v.x, v.y);
        *(__half2*)(dst + i + 2) = __floats2half2_rn(v.z, v.w);
    }
}

// ---------------- LN + modulation -> fp16 xmod -----------------------------------
__global__ void ln_mod_kernel(const float* __restrict__ txt_emb,
                              const float* __restrict__ img_emb,
                              const float* __restrict__ tsc, const float* __restrict__ tsh,
                              const float* __restrict__ isc, const float* __restrict__ ish)
{
    int l = blockIdx.x, tid = threadIdx.x;
    __shared__ float row[DIMC];
    __shared__ float redA[8], redB[8];

    const float *x, *sc, *sh;
    if (l < L_TXTC) { x = txt_emb + (long)l * DIMC; sc = tsc; sh = tsh; }
    else            { x = img_emb + (long)(l - L_TXTC) * DIMC; sc = isc; sh = ish; }

    float s = 0.f, s2 = 0.f;
    for (int i = tid; i < DIMC; i += 256) {
        float v = x[i]; row[i] = v; s += v; s2 += v * v;
    }
#pragma unroll
    for (int o = 16; o > 0; o >>= 1) {
        s  += __shfl_xor_sync(0xffffffffu, s,  o);
        s2 += __shfl_xor_sync(0xffffffffu, s2, o);
    }
    int w = tid >> 5;
    if ((tid & 31) == 0) { redA[w] = s; redB[w] = s2; }
    __syncthreads();
    if (tid == 0) {
        float a = 0.f, b = 0.f;
        for (int i = 0; i < 8; i++) { a += redA[i]; b += redB[i]; }
        redA[0] = a; redB[0] = b;
    }
    __syncthreads();
    float mean = redA[0] / DIMC;
    float var  = redB[0] / DIMC - mean * mean;
    float rstd = rsqrtf(var + 1e-6f);

    __half* out = g_xmod + (long)l * DIMC;
    for (int i = tid; i < DIMC; i += 256)
        out[i] = __float2half((1.0f + sc[i]) * ((row[i] - mean) * rstd) + sh[i]);
}

// ---------------- QKV post: shuffle-based RMSNorm + RoPE + fp16 transpose ---------
__global__ void qkv_post_kernel(const float* __restrict__ pe,
                                const float* __restrict__ tqw,
                                const float* __restrict__ iqw)
{
    int l = blockIdx.x, h = blockIdx.y, d = threadIdx.x;
    int lane = d & 31, warp = d >> 5;
    const __half* base = g_qkv + (long)l * QKVD + h * DHC;
    float qv = __half2float(base[d]);
    float kv = __half2float(base[DIMC + d]);
    float vv = __half2float(base[2 * DIMC + d]);
    const float* w = (l < L_TXTC) ? tqw : iqw;

    float a = qv * qv, b = kv * kv;
#pragma unroll
    for (int o = 16; o > 0; o >>= 1) {
        a += __shfl_xor_sync(0xffffffffu, a, o);
        b += __shfl_xor_sync(0xffffffffu, b, o);
    }
    __shared__ float ra[4], rb[4];
    if (lane == 0) { ra[warp] = a; rb[warp] = b; }
    __syncthreads();
    a = ra[0] + ra[1] + ra[2] + ra[3];
    b = rb[0] + rb[1] + rb[2] + rb[3];
    float rq = rsqrtf(a / DHC + 1e-6f);
    float rk = rsqrtf(b / DHC + 1e-6f);

    float xq = qv * rq * w[d];
    float xk = kv * rk * w[d];
    float pq = __shfl_xor_sync(0xffffffffu, xq, 1);
    float pk = __shfl_xor_sync(0xffffffffu, xk, 1);

    int j = d >> 1;
    float c = pe[(long)l * 256 + j * 4];
    float s = pe[(long)l * 256 + j * 4 + 2];
    float qr, kr;
    if ((d & 1) == 0) {
        qr = xq * c - pq * s;
        kr = xk * c - pk * s;
    } else {
        qr = pq * s + xq * c;
        kr = pk * s + xk * c;
    }
    long qi = ((long)h * L_ALLC + l) * DHC + d;
    g_q[qi] = __float2half(qr * 0.08838834764831845f);  // DH^-0.5 folded into q
    g_k[qi] = __float2half(kr);
    g_vt[((long)h * DHC + d) * L_ALLC + l] = __float2half(vv);
}

// ---------------- residual + LN + MLP modulation (fp16 mlpin; xres saved) ---------
__global__ void res_ln_kernel(const float* __restrict__ txt_emb,
                              const float* __restrict__ img_emb,
                              const float* __restrict__ tgate, const float* __restrict__ igate,
                              const float* __restrict__ tmsc,  const float* __restrict__ tmsh,
                              const float* __restrict__ imsc,  const float* __restrict__ imsh)
{
    int l = blockIdx.x, tid = threadIdx.x;
    __shared__ float row[DIMC];
    __shared__ float redA[8], redB[8];

    const float *emb, *gate, *msc, *msh;
    if (l < L_TXTC) { emb = txt_emb + (long)l * DIMC; gate = tgate; msc = tmsc; msh = tmsh; }
    else            { emb = img_emb + (long)(l - L_TXTC) * DIMC; gate = igate; msc = imsc; msh = imsh; }

    const float* attn = g_attno + (long)l * DIMC;
    float* xres = g_xres + (long)l * DIMC;

    float s = 0.f, s2 = 0.f;
    for (int i = tid; i < DIMC; i += 256) {
        float v = emb[i] + gate[i] * attn[i];
        row[i] = v; xres[i] = v; s += v; s2 += v * v;
    }
#pragma unroll
    for (int o = 16; o > 0; o >>= 1) {
        s  += __shfl_xor_sync(0xffffffffu, s,  o);
        s2 += __shfl_xor_sync(0xffffffffu, s2, o);
    }
    int w = tid >> 5;
    if ((tid & 31) == 0) { redA[w] = s; redB[w] = s2; }
    __syncthreads();
    if (tid == 0) {
        float a = 0.f, b = 0.f;
        for (int i = 0; i < 8; i++) { a += redA[i]; b += redB[i]; }
        redA[0] = a; redB[0] = b;
    }
    __syncthreads();
    float mean = redA[0] / DIMC;
    float var  = redB[0] / DIMC - mean * mean;
    float rstd = rsqrtf(var + 1e-6f);

    __half* out = g_mlpin + (long)l * DIMC;
    for (int i = tid; i < DIMC; i += 256)
        out[i] = __float2half((1.0f + msc[i]) * ((row[i] - mean) * rstd) + msh[i]);
}

// ---------------- host ----------------------------------------------------------
static void hgemm(const __half* A, long lda,
                  const __half* B1, const __half* B2, long ldb,
                  const float* bias1, const float* bias2, int mSplit,
                  void* C, long ldc, int M, int N, int K, int cmode,
                  const float* res = nullptr,
                  const float* gate1 = nullptr, const float* gate2 = nullptr)
{
    dim3 grid((M / 128) * (N / 128), 1, 1);
    gemm_f16_kernel<<<grid, 256, GSMEM_BYTES>>>(A, lda, B1, B2, ldb,
                                                bias1, bias2, mSplit,
                                                C, ldc, M, K, cmode,
                                                res, gate1, gate2);
}

static void f2h(const float* src, __half* dst, long n)
{
    f2h_kernel<<<(unsigned)((n / 4 + 255) / 256), 256>>>(src, dst, (int)n);
}

extern "C" void kernel_launch(void* const* d_in, const int* in_sizes, int n_in,
                              void* d_out, int out_size)
{
    cudaFuncSetAttribute(gemm_f16_kernel,
                         cudaFuncAttributeMaxDynamicSharedMemorySize, GSMEM_BYTES);
    cudaFuncSetAttribute(flash_attn_kernel,
                         cudaFuncAttributeMaxDynamicSharedMemorySize, FA_SMEM);

    const float* img_emb = (const float*)d_in[0];
    const float* txt_emb = (const float*)d_in[1];
    const float* pe      = (const float*)d_in[2];
    const float* i_asc = (const float*)d_in[3];
    const float* i_ash = (const float*)d_in[4];
    const float* i_ag  = (const float*)d_in[5];
    const float* i_msc = (const float*)d_in[6];
    const float* i_msh = (const float*)d_in[7];
    const float* i_mg  = (const float*)d_in[8];
    const float* t_asc = (const float*)d_in[9];
    const float* t_ash = (const float*)d_in[10];
    const float* t_ag  = (const float*)d_in[11];
    const float* t_msc = (const float*)d_in[12];
    const float* t_msh = (const float*)d_in[13];
    const float* t_mg  = (const float*)d_in[14];
    const float* i_qkv_w = (const float*)d_in[15];
    const float* i_qkv_b = (const float*)d_in[16];
    const float* i_qnw   = (const float*)d_in[17];
    const float* t_qkv_w = (const float*)d_in[18];
    const float* t_qkv_b = (const float*)d_in[19];
    const float* t_qnw   = (const float*)d_in[20];
    const float* proj_w  = (const float*)d_in[21];
    const float* proj_b  = (const float*)d_in[22];
    const float* i_w1 = (const float*)d_in[23];
    const float* i_b1 = (const float*)d_in[24];
    const float* i_w2 = (const float*)d_in[25];
    const float* i_b2 = (const float*)d_in[26];
    const float* t_w1 = (const float*)d_in[27];
    const float* t_b1 = (const float*)d_in[28];
    const float* t_w2 = (const float*)d_in[29];
    const float* t_b2 = (const float*)d_in[30];
    // d_in[31] = mask: all-true in this problem -> no-op in attention.

    float *p_attno, *p_xres;
    __half *p_xmod, *p_qkv, *p_ocat, *p_mlpin, *p_hid;
    __half *w_qkv_t, *w_qkv_i, *w_proj, *w_w1t, *w_w1i, *w_w2t, *w_w2i;
    cudaGetSymbolAddress((void**)&p_xmod,  g_xmod);
    cudaGetSymbolAddress((void**)&p_qkv,   g_qkv);
    cudaGetSymbolAddress((void**)&p_ocat,  g_ocat);
    cudaGetSymbolAddress((void**)&p_attno, g_attno);
    cudaGetSymbolAddress((void**)&p_xres,  g_xres);
    cudaGetSymbolAddress((void**)&p_mlpin, g_mlpin);
    cudaGetSymbolAddress((void**)&p_hid,   g_hid);
    cudaGetSymbolAddress((void**)&w_qkv_t, g_hw_qkv_t);
    cudaGetSymbolAddress((void**)&w_qkv_i, g_hw_qkv_i);
    cudaGetSymbolAddress((void**)&w_proj,  g_hw_proj);
    cudaGetSymbolAddress((void**)&w_w1t,   g_hw_w1t);
    cudaGetSymbolAddress((void**)&w_w1i,   g_hw_w1i);
    cudaGetSymbolAddress((void**)&w_w2t,   g_hw_w2t);
    cudaGetSymbolAddress((void**)&w_w2i,   g_hw_w2i);

    float* out = (float*)d_out;

    // 0. convert weights to fp16
    f2h(t_qkv_w, w_qkv_t, (long)QKVD * DIMC);
    f2h(i_qkv_w, w_qkv_i, (long)QKVD * DIMC);
    f2h(proj_w,  w_proj,  (long)DIMC * DIMC);
    f2h(t_w1,    w_w1t,   (long)MLPD * DIMC);
    f2h(i_w1,    w_w1i,   (long)MLPD * DIMC);
    f2h(t_w2,    w_w2t,   (long)DIMC * MLPD);
    f2h(i_w2,    w_w2i,   (long)DIMC * MLPD);

    // 1. LN + attn modulation -> fp16 xmod (txt rows first, then img)
    ln_mod_kernel<<<L_ALLC, 256>>>(txt_emb, img_emb, t_asc, t_ash, i_asc, i_ash);

    // 2. fused QKV GEMM (txt m-tiles 0-3, img m-tiles 4-15)
    hgemm(p_xmod, DIMC, w_qkv_t, w_qkv_i, DIMC, t_qkv_b, i_qkv_b, L_TXTC / 128,
          p_qkv, QKVD, L_ALLC, QKVD, DIMC, 2);

    // 3. RMSNorm + RoPE + scale + fp16 layout
    {
        dim3 grid(L_ALLC, NH);
        qkv_post_kernel<<<grid, DHC>>>(pe, t_qnw, i_qnw);
    }

    // 4. fused flash attention -> fp16 ocat
    {
        dim3 grid(L_ALLC / 128, NH);
        flash_attn_kernel<<<grid, 256, FA_SMEM>>>();
    }

    // 5. shared proj (fp32 out)
    hgemm(p_ocat, DIMC, w_proj, w_proj, DIMC, proj_b, proj_b, L_ALLC / 128,
          p_attno, DIMC, L_ALLC, DIMC, DIMC, 0);

    // 6. residual + LN + mlp modulation -> fp16 mlpin (+ xres)
    res_ln_kernel<<<L_ALLC, 256>>>(txt_emb, img_emb, t_ag, i_ag, t_msc, t_msh, i_msc, i_msh);

    // 7. fused MLP up + GELU -> fp16 hid
    hgemm(p_mlpin, DIMC, w_w1t, w_w1i, DIMC, t_b1, i_b1, L_TXTC / 128,
          p_hid, MLPD, L_ALLC, MLPD, DIMC, 3);

    // 8. fused MLP down + gate + residual + output remap (img first, then txt)
    hgemm(p_hid, MLPD, w_w2t, w_w2i, MLPD, t_b2, i_b2, L_TXTC / 128,
          out, DIMC, L_ALLC, DIMC, MLPD, 4, p_xres, t_mg, i_mg);
}

// round 16
// speedup vs baseline: 1.0995x; 1.0228x over previous
#include <cuda_runtime.h>
#include <cuda_fp16.h>
#include <math.h>
#include <stdint.h>

#define L_ALLC 2048
#define L_TXTC 512
#define L_IMGC 1536
#define NH     24
#define DHC    128
#define DIMC   3072
#define QKVD   9216
#define MLPD   12288

// ---------------- scratch (device globals; no runtime allocation) ----------------
__device__ __half g_xmod [L_ALLC * DIMC];
__device__ __half g_qkv  [L_ALLC * QKVD];
__device__ __half g_q    [NH * L_ALLC * DHC];
__device__ __half g_k    [NH * L_ALLC * DHC];
__device__ __half g_vt   [NH * DHC * L_ALLC];
__device__ __half g_ocat [L_ALLC * DIMC];
__device__ float  g_attno[L_ALLC * DIMC];
__device__ float  g_xres [L_ALLC * DIMC];
__device__ __half g_mlpin[L_ALLC * DIMC];
__device__ __half g_hid  [L_ALLC * MLPD];
// fp16 weight mirrors (converted each launch)
__device__ __half g_hw_qkv_t[QKVD * DIMC];
__device__ __half g_hw_qkv_i[QKVD * DIMC];
__device__ __half g_hw_proj [DIMC * DIMC];
__device__ __half g_hw_w1t  [MLPD * DIMC];
__device__ __half g_hw_w1i  [MLPD * DIMC];
__device__ __half g_hw_w2t  [DIMC * MLPD];
__device__ __half g_hw_w2i  [DIMC * MLPD];

__device__ __forceinline__ float gelu_tanh(float x) {
    float x3 = x * x * x;
    return 0.5f * x * (1.0f + tanhf(0.7978845608028654f * (x + 0.044715f * x3)));
}

__device__ __forceinline__ void cp_async16(unsigned smem_addr, const void* gptr) {
    asm volatile("cp.async.cg.shared.global [%0], [%1], 16;\n"
                 :: "r"(smem_addr), "l"(gptr));
}
__device__ __forceinline__ void cp_commit() {
    asm volatile("cp.async.commit_group;\n");
}
__device__ __forceinline__ void cp_wait1() {
    asm volatile("cp.async.wait_group 1;\n");
}
__device__ __forceinline__ void cp_wait2() {
    asm volatile("cp.async.wait_group 2;\n");
}

__device__ __forceinline__ void ldsm_x4(unsigned& r0, unsigned& r1,
                                        unsigned& r2, unsigned& r3, unsigned addr) {
    asm volatile("ldmatrix.sync.aligned.m8n8.x4.shared.b16 {%0,%1,%2,%3}, [%4];"
                 : "=r"(r0), "=r"(r1), "=r"(r2), "=r"(r3) : "r"(addr));
}

#define MMA16816(acc, a0, a1, a2, a3, b0, b1)                                  \
    asm volatile(                                                              \
        "mma.sync.aligned.m16n8k16.row.col.f32.f16.f16.f32 "                   \
        "{%0,%1,%2,%3}, {%4,%5,%6,%7}, {%8,%9}, {%0,%1,%2,%3};"                \
        : "+f"((acc)[0]), "+f"((acc)[1]), "+f"((acc)[2]), "+f"((acc)[3])       \
        : "r"(a0), "r"(a1), "r"(a2), "r"(a3), "r"(b0), "r"(b1))

// ---------------- fp16 mma GEMM, 128x128 CTA tile, BK=64, 3-stage ring -----------
// 256 threads, 8 warps in 2x4, warp tile 64x32.
// Dual weight set: m-tiles < mSplit use B1/bias1, rest B2/bias2.
// cmode: 0 f32 out, 1 f32+gelu, 2 half out, 3 half+gelu,
//        4 final: out = res + gate*(acc+bias), img-first/txt-second row remap.
#define MAT_BYTES   (128 * 72 * 2)
#define STAGE_BYTES (2 * MAT_BYTES)
#define GSMEM_BYTES (3 * STAGE_BYTES)

__global__ __launch_bounds__(256, 2)
void gemm_f16_kernel(const __half* __restrict__ A, long lda,
                     const __half* __restrict__ B1, const __half* __restrict__ B2,
                     long ldb,
                     const float* __restrict__ bias1, const float* __restrict__ bias2,
                     int mSplit,
                     void* __restrict__ Cv, long ldc,
                     int M, int K, int cmode,
                     const float* __restrict__ res,
                     const float* __restrict__ gate1, const float* __restrict__ gate2)
{
    extern __shared__ float sm[];
    const unsigned sbase = (unsigned)__cvta_generic_to_shared(sm);

    const int tid = threadIdx.x;
    const int nm = M >> 7;
    const int bm = blockIdx.x % nm;     // M fastest
    const int bn = blockIdx.x / nm;

    const __half* Ag = A + (long)bm * 128 * lda;
    const __half* Bg = (bm < mSplit ? B1 : B2) + (long)bn * 128 * ldb;
    const float*  bias = (bm < mSplit) ? bias1 : bias2;
    const float*  gate = (bm < mSplit) ? gate1 : gate2;

    const int lane = tid & 31;
    const int warp = tid >> 5;
    const int wm = (warp >> 2) * 64;
    const int wn = (warp & 3) * 32;
    const int qr = lane >> 2;
    const int qc = lane & 3;

    const int prow[4] = { (tid + 0) >> 3, (tid + 256) >> 3, (tid + 512) >> 3, (tid + 768) >> 3 };
    const int pc8 = (tid & 7) * 8;
    const unsigned poff[4] = {
        (unsigned)(prow[0] * 72 + pc8) * 2u, (unsigned)(prow[1] * 72 + pc8) * 2u,
        (unsigned)(prow[2] * 72 + pc8) * 2u, (unsigned)(prow[3] * 72 + pc8) * 2u };

    const unsigned a_off =
        (unsigned)(((wm + (lane & 7) + ((lane >> 3) & 1) * 8) * 72 + (lane >> 4) * 8) * 2);
    const unsigned b_off = MAT_BYTES +
        (unsigned)(((wn + (lane & 7) + (lane >> 4) * 8) * 72 + ((lane >> 3) & 1) * 8) * 2);

    float acc[4][4][4];
#pragma unroll
    for (int mi = 0; mi < 4; mi++)
#pragma unroll
        for (int ni = 0; ni < 4; ni++)
#pragma unroll
            for (int e = 0; e < 4; e++) acc[mi][ni][e] = 0.0f;

    const int T = K >> 6;

    #define LOAD_SLAB(so, k0)                                                    \
    do {                                                                         \
        unsigned _a = sbase + (so), _b = _a + MAT_BYTES;                         \
        _Pragma("unroll")                                                        \
        for (int r = 0; r < 4; r++) {                                            \
            cp_async16(_a + poff[r], Ag + (long)prow[r] * lda + (k0) + pc8);     \
            cp_async16(_b + poff[r], Bg + (long)prow[r] * ldb + (k0) + pc8);     \
        }                                                                        \
    } while (0)

    LOAD_SLAB(0, 0);
    cp_commit();
    LOAD_SLAB(STAGE_BYTES, 64);
    cp_commit();

    unsigned so_c = 0;
    unsigned so_l = 2 * STAGE_BYTES;
    for (int t = 0; t < T; t++) {
        if (t + 2 < T) LOAD_SLAB(so_l, (t + 2) << 6);
        cp_commit();
        cp_wait2();
        __syncthreads();

        const unsigned abase = sbase + so_c + a_off;
        const unsigned bbase = sbase + so_c + b_off;

#pragma unroll
        for (int ks = 0; ks < 64; ks += 16) {
            unsigned a[4][4], b[4][2];
#pragma unroll
            for (int mi = 0; mi < 4; mi++)
                ldsm_x4(a[mi][0], a[mi][1], a[mi][2], a[mi][3],
                        abase + (unsigned)((mi * 16 * 72 + ks) * 2));
            ldsm_x4(b[0][0], b[0][1], b[1][0], b[1][1],
                    bbase + (unsigned)(ks * 2));
            ldsm_x4(b[2][0], b[2][1], b[3][0], b[3][1],
                    bbase + (unsigned)((16 * 72 + ks) * 2));
#pragma unroll
            for (int mi = 0; mi < 4; mi++)
#pragma unroll
                for (int ni = 0; ni < 4; ni++)
                    MMA16816(acc[mi][ni], a[mi][0], a[mi][1], a[mi][2], a[mi][3],
                             b[ni][0], b[ni][1]);
        }
        __syncthreads();

        so_c += STAGE_BYTES; if (so_c == GSMEM_BYTES) so_c = 0;
        so_l += STAGE_BYTES; if (so_l == GSMEM_BYTES) so_l = 0;
    }

    // ---- epilogue ----
#pragma unroll
    for (int ni = 0; ni < 4; ni++) {
        int col = wn + ni * 8 + qc * 2;
        float b0 = bias ? bias[(long)bn * 128 + col]     : 0.0f;
        float b1 = bias ? bias[(long)bn * 128 + col + 1] : 0.0f;
#pragma unroll
        for (int mi = 0; mi < 4; mi++) {
            int row = wm + mi * 16 + qr;
            float t0 = acc[mi][ni][0] + b0;
            float t1 = acc[mi][ni][1] + b1;
            float t2 = acc[mi][ni][2] + b0;
            float t3 = acc[mi][ni][3] + b1;
            if (cmode == 1 || cmode == 3) {
                t0 = gelu_tanh(t0); t1 = gelu_tanh(t1);
                t2 = gelu_tanh(t2); t3 = gelu_tanh(t3);
            }
            if (cmode == 4) {
                long gcol = (long)bn * 128 + col;
                float gv0 = gate[gcol], gv1 = gate[gcol + 1];
                int l0 = bm * 128 + row;
                int l1 = l0 + 8;
                const float* r0 = res + (long)l0 * ldc + gcol;
                const float* r1 = res + (long)l1 * ldc + gcol;
                long d0 = (l0 < L_TXTC) ? (long)(L_IMGC + l0) : (long)(l0 - L_TXTC);
                long d1 = (l1 < L_TXTC) ? (long)(L_IMGC + l1) : (long)(l1 - L_TXTC);
                float* Cf = (float*)Cv;
                *(float2*)(Cf + d0 * ldc + gcol) =
                    make_float2(r0[0] + gv0 * t0, r0[1] + gv1 * t1);
                *(float2*)(Cf + d1 * ldc + gcol) =
                    make_float2(r1[0] + gv0 * t2, r1[1] + gv1 * t3);
            } else if (cmode < 2) {
                float* Cf = (float*)Cv + (long)bm * 128 * ldc + (long)bn * 128;
                *(float2*)(Cf + (long)row * ldc + col)       = make_float2(t0, t1);
                *(float2*)(Cf + (long)(row + 8) * ldc + col) = make_float2(t2, t3);
            } else {
                __half* Ch = (__half*)Cv + (long)bm * 128 * ldc + (long)bn * 128;
                *(__half2*)(Ch + (long)row * ldc + col)       = __floats2half2_rn(t0, t1);
                *(__half2*)(Ch + (long)(row + 8) * ldc + col) = __floats2half2_rn(t2, t3);
            }
        }
    }
    #undef LOAD_SLAB
}

// ---------------- fused flash attention ------------------------------------------
#define FA_QB 34816u                        // 128*136*2
#define FA_SMEM (5 * FA_QB)                 // 174080

__global__ __launch_bounds__(256, 1)
void flash_attn_kernel()
{
    extern __shared__ char fsm[];
    const unsigned sbase = (unsigned)__cvta_generic_to_shared(fsm);
    const int tid = threadIdx.x, lane = tid & 31, warp = tid >> 5;
    const int bm = blockIdx.x, h = blockIdx.y;

    const __half* Qg = g_q + ((long)h * L_ALLC + (long)bm * 128) * DHC;
    const __half* Kg = g_k + (long)h * L_ALLC * DHC;
    const __half* Vg = g_vt + (long)h * DHC * L_ALLC;   // [d][l]

    const unsigned sQ  = sbase;
    const unsigned sK0 = sbase + FA_QB,     sK1 = sK0 + FA_QB;
    const unsigned sV0 = sK1 + FA_QB,       sV1 = sV0 + FA_QB;

#pragma unroll
    for (int i = 0; i < 8; i++) {
        int c = tid + i * 256;
        int row = c >> 4, col = (c & 15) * 8;
        cp_async16(sQ + (unsigned)(row * 136 + col) * 2, Qg + (long)row * DHC + col);
    }
    cp_commit();

    #define FA_LOAD(sk, sv, t)                                                      \
    do {                                                                            \
        const __half* kp = Kg + (long)(t) * 128 * DHC;                              \
        const __half* vp = Vg + (t) * 128;                                          \
        _Pragma("unroll")                                                           \
        for (int i = 0; i < 8; i++) {                                               \
            int c = tid + i * 256;                                                  \
            int row = c >> 4, col = (c & 15) * 8;                                   \
            unsigned so = (unsigned)(row * 136 + col) * 2;                          \
            cp_async16((sk) + so, kp + (long)row * DHC + col);                      \
            cp_async16((sv) + so, vp + (long)row * L_ALLC + col);                   \
        }                                                                           \
    } while (0)

    FA_LOAD(sK0, sV0, 0);
    cp_commit();

    const int qr = lane >> 2, qc = lane & 3;
    const unsigned a_off =
        (unsigned)(((warp * 16 + (lane & 7) + ((lane >> 3) & 1) * 8) * 136 + (lane >> 4) * 8) * 2);
    const unsigned b_off =
        (unsigned)((((lane & 7) + (lane >> 4) * 8) * 136 + ((lane >> 3) & 1) * 8) * 2);

    float oacc[16][4];
#pragma unroll
    for (int n = 0; n < 16; n++)
#pragma unroll
        for (int e = 0; e < 4; e++) oacc[n][e] = 0.0f;
    float mrow[2] = { -1e30f, -1e30f };
    float lrow[2] = { 0.0f, 0.0f };

    const int NT = L_ALLC / 128;   // 16
    for (int t = 0; t < NT; t++) {
        if (t + 1 < NT) {
            if (t & 1) FA_LOAD(sK0, sV0, t + 1);
            else       FA_LOAD(sK1, sV1, t + 1);
        }
        cp_commit();
        cp_wait1();
        __syncthreads();

        const unsigned kb = (t & 1) ? sK1 : sK0;
        const unsigned vb = (t & 1) ? sV1 : sV0;

        float sacc[16][4];
#pragma unroll
        for (int n = 0; n < 16; n++)
#pragma unroll
            for (int e = 0; e < 4; e++) sacc[n][e] = 0.0f;

#pragma unroll
        for (int ks = 0; ks < 8; ks++) {
            unsigned a0, a1, a2, a3;
            ldsm_x4(a0, a1, a2, a3, sQ + a_off + (unsigned)(ks * 32));
#pragma unroll
            for (int nj = 0; nj < 8; nj++) {
                unsigned b0, b1, b2, b3;
                ldsm_x4(b0, b1, b2, b3,
                        kb + b_off + (unsigned)(nj * 16 * 136 * 2 + ks * 32));
                MMA16816(sacc[2 * nj],     a0, a1, a2, a3, b0, b1);
                MMA16816(sacc[2 * nj + 1], a0, a1, a2, a3, b2, b3);
            }
        }

#pragma unroll
        for (int g = 0; g < 2; g++) {
            float mx = -1e30f;
#pragma unroll
            for (int n = 0; n < 16; n++)
                mx = fmaxf(mx, fmaxf(sacc[n][2 * g], sacc[n][2 * g + 1]));
            mx = fmaxf(mx, __shfl_xor_sync(0xffffffffu, mx, 1));
            mx = fmaxf(mx, __shfl_xor_sync(0xffffffffu, mx, 2));
            float nm = fmaxf(mrow[g], mx);
            float sc = __expf(mrow[g] - nm);
            mrow[g] = nm;
            float rs = 0.0f;
#pragma unroll
            for (int n = 0; n < 16; n++) {
                float e0 = __expf(sacc[n][2 * g] - nm);
                float e1 = __expf(sacc[n][2 * g + 1] - nm);
                sacc[n][2 * g] = e0; sacc[n][2 * g + 1] = e1;
                rs += e0 + e1;
            }
            rs += __shfl_xor_sync(0xffffffffu, rs, 1);
            rs += __shfl_xor_sync(0xffffffffu, rs, 2);
            lrow[g] = lrow[g] * sc + rs;
#pragma unroll
            for (int n = 0; n < 16; n++) {
                oacc[n][2 * g]     *= sc;
                oacc[n][2 * g + 1] *= sc;
            }
        }

        unsigned p[16][2];
#pragma unroll
        for (int n = 0; n < 16; n++) {
            __half2 h0 = __floats2half2_rn(sacc[n][0], sacc[n][1]);
            __half2 h1 = __floats2half2_rn(sacc[n][2], sacc[n][3]);
            p[n][0] = *(unsigned*)&h0;
            p[n][1] = *(unsigned*)&h1;
        }

#pragma unroll
        for (int ks = 0; ks < 8; ks++) {
            unsigned a0 = p[2 * ks][0], a1 = p[2 * ks][1];
            unsigned a2 = p[2 * ks + 1][0], a3 = p[2 * ks + 1][1];
#pragma unroll
            for (int nj = 0; nj < 8; nj++) {
                unsigned b0, b1, b2, b3;
                ldsm_x4(b0, b1, b2, b3,
                        vb + b_off + (unsigned)(nj * 16 * 136 * 2 + ks * 32));
                MMA16816(oacc[2 * nj],     a0, a1, a2, a3, b0, b1);
                MMA16816(oacc[2 * nj + 1], a0, a1, a2, a3, b2, b3);
            }
        }
        __syncthreads();
    }

    float inv0 = 1.0f / lrow[0];
    float inv1 = 1.0f / lrow[1];
    __half* Og = g_ocat + (long)(bm * 128 + warp * 16) * DIMC + h * DHC;
#pragma unroll
    for (int n = 0; n < 16; n++) {
        int col = n * 8 + qc * 2;
        *(__half2*)(Og + (long)qr * DIMC + col) =
            __floats2half2_rn(oacc[n][0] * inv0, oacc[n][1] * inv0);
        *(__half2*)(Og + (long)(qr + 8) * DIMC + col) =
            __floats2half2_rn(oacc[n][2] * inv1, oacc[n][3] * inv1);
    }
    #undef FA_LOAD
}

// ---------------- fp32 -> fp16 convert -------------------------------------------
__global__ __launch_bounds__(256)
void f2h_kernel(const float* __restrict__ src, __half* __restrict__ dst, int n)
{
    int i = (blockIdx.x * 256 + threadIdx.x) * 4;
    if (i < n) {
        float4 v = *(const float4*)(src + i);
        *(__half2*)(dst + i)     = __floats2half2_rn(v.x, v.y);
        *(__half2*)(dst + i + 2) = __floats2half2_rn(v.z, v.w);
    }
}

// ---------------- LN + modulation -> fp16 xmod -----------------------------------
__global__ void ln_mod_kernel(const float* __restrict__ txt_emb,
                              const float* __restrict__ img_emb,
                              const float* __restrict__ tsc, const float* __restrict__ tsh,
                              const float* __restrict__ isc, const float* __restrict__ ish)
{
    int l = blockIdx.x, tid = threadIdx.x;
    __shared__ float row[DIMC];
    __shared__ float redA[8], redB[8];

    const float *x, *sc, *sh;
    if (l < L_TXTC) { x = txt_emb + (long)l * DIMC; sc = tsc; sh = tsh; }
    else            { x = img_emb + (long)(l - L_TXTC) * DIMC; sc = isc; sh = ish; }

    float s = 0.f, s2 = 0.f;
    for (int i = tid; i < DIMC; i += 256) {
        float v = x[i]; row[i] = v; s += v; s2 += v * v;
    }
#pragma unroll
    for (int o = 16; o > 0; o >>= 1) {
        s  += __shfl_xor_sync(0xffffffffu, s,  o);
        s2 += __shfl_xor_sync(0xffffffffu, s2, o);
    }
    int w = tid >> 5;
    if ((tid & 31) == 0) { redA[w] = s; redB[w] = s2; }
    __syncthreads();
    if (tid == 0) {
        float a = 0.f, b = 0.f;
        for (int i = 0; i < 8; i++) { a += redA[i]; b += redB[i]; }
        redA[0] = a; redB[0] = b;
    }
    __syncthreads();
    float mean = redA[0] / DIMC;
    float var  = redB[0] / DIMC - mean * mean;
    float rstd = rsqrtf(var + 1e-6f);

    __half* out = g_xmod + (long)l * DIMC;
    for (int i = tid; i < DIMC; i += 256)
        out[i] = __float2half((1.0f + sc[i]) * ((row[i] - mean) * rstd) + sh[i]);
}

// ---------------- QKV post: shuffle-based RMSNorm + RoPE + fp16 transpose ---------
__global__ void qkv_post_kernel(const float* __restrict__ pe,
                                const float* __restrict__ tqw,
                                const float* __restrict__ iqw)
{
    int l = blockIdx.x, h = blockIdx.y, d = threadIdx.x;
    int lane = d & 31, warp = d >> 5;
    const __half* base = g_qkv + (long)l * QKVD + h * DHC;
    float qv = __half2float(base[d]);
    float kv = __half2float(base[DIMC + d]);
    float vv = __half2float(base[2 * DIMC + d]);
    const float* w = (l < L_TXTC) ? tqw : iqw;

    float a = qv * qv, b = kv * kv;
#pragma unroll
    for (int o = 16; o > 0; o >>= 1) {
        a += __shfl_xor_sync(0xffffffffu, a, o);
        b += __shfl_xor_sync(0xffffffffu, b, o);
    }
    __shared__ float ra[4], rb[4];
    if (lane == 0) { ra[warp] = a; rb[warp] = b; }
    __syncthreads();
    a = ra[0] + ra[1] + ra[2] + ra[3];
    b = rb[0] + rb[1] + rb[2] + rb[3];
    float rq = rsqrtf(a / DHC + 1e-6f);
    float rk = rsqrtf(b / DHC + 1e-6f);

    float xq = qv * rq * w[d];
    float xk = kv * rk * w[d];
    float pq = __shfl_xor_sync(0xffffffffu, xq, 1);
    float pk = __shfl_xor_sync(0xffffffffu, xk, 1);

    int j = d >> 1;
    float c = pe[(long)l * 256 + j * 4];
    float s = pe[(long)l * 256 + j * 4 + 2];
    float qr, kr;
    if ((d & 1) == 0) {
        qr = xq * c - pq * s;
        kr = xk * c - pk * s;
    } else {
        qr = pq * s + xq * c;
        kr = pk * s + xk * c;
    }
    long qi = ((long)h * L_ALLC + l) * DHC + d;
    g_q[qi] = __float2half(qr * 0.08838834764831845f);  // DH^-0.5 folded into q
    g_k[qi] = __float2half(kr);
    g_vt[((long)h * DHC + d) * L_ALLC + l] = __float2half(vv);
}

// ---------------- residual + LN + MLP modulation (fp16 mlpin; xres saved) ---------
__global__ void res_ln_kernel(const float* __restrict__ txt_emb,
                              const float* __restrict__ img_emb,
                              const float* __restrict__ tgate, const float* __restrict__ igate,
                              const float* __restrict__ tmsc,  const float* __restrict__ tmsh,
                              const float* __restrict__ imsc,  const float* __restrict__ imsh)
{
    int l = blockIdx.x, tid = threadIdx.x;
    __shared__ float row[DIMC];
    __shared__ float redA[8], redB[8];

    const float *emb, *gate, *msc, *msh;
    if (l < L_TXTC) { emb = txt_emb + (long)l * DIMC; gate = tgate; msc = tmsc; msh = tmsh; }
    else            { emb = img_emb + (long)(l - L_TXTC) * DIMC; gate = igate; msc = imsc; msh = imsh; }

    const float* attn = g_attno + (long)l * DIMC;
    float* xres = g_xres + (long)l * DIMC;

    float s = 0.f, s2 = 0.f;
    for (int i = tid; i < DIMC; i += 256) {
        float v = emb[i] + gate[i] * attn[i];
        row[i] = v; xres[i] = v; s += v; s2 += v * v;
    }
#pragma unroll
    for (int o = 16; o > 0; o >>= 1) {
        s  += __shfl_xor_sync(0xffffffffu, s,  o);
        s2 += __shfl_xor_sync(0xffffffffu, s2, o);
    }
    int w = tid >> 5;
    if ((tid & 31) == 0) { redA[w] = s; redB[w] = s2; }
    __syncthreads();
    if (tid == 0) {
        float a = 0.f, b = 0.f;
        for (int i = 0; i < 8; i++) { a += redA[i]; b += redB[i]; }
        redA[0] = a; redB[0] = b;
    }
    __syncthreads();
    float mean = redA[0] / DIMC;
    float var  = redB[0] / DIMC - mean * mean;
    float rstd = rsqrtf(var + 1e-6f);

    __half* out = g_mlpin + (long)l * DIMC;
    for (int i = tid; i < DIMC; i += 256)
        out[i] = __float2half((1.0f + msc[i]) * ((row[i] - mean) * rstd) + msh[i]);
}

// ---------------- host ----------------------------------------------------------
static void hgemm(const __half* A, long lda,
                  const __half* B1, const __half* B2, long ldb,
                  const float* bias1, const float* bias2, int mSplit,
                  void* C, long ldc, int M, int N, int K, int cmode,
                  const float* res = nullptr,
                  const float* gate1 = nullptr, const float* gate2 = nullptr)
{
    dim3 grid((M / 128) * (N / 128), 1, 1);
    gemm_f16_kernel<<<grid, 256, GSMEM_BYTES>>>(A, lda, B1, B2, ldb,
                                                bias1, bias2, mSplit,
                                                C, ldc, M, K, cmode,
                                                res, gate1, gate2);
}

static void f2h_on(cudaStream_t st, const float* src, __half* dst, long n)
{
    f2h_kernel<<<(unsigned)((n / 4 + 255) / 256), 256, 0, st>>>(src, dst, (int)n);
}

extern "C" void kernel_launch(void* const* d_in, const int* in_sizes, int n_in,
                              void* d_out, int out_size)
{
    // side stream + events, created once on the first (non-capture) call.
    static cudaStream_t s2 = [] {
        cudaStream_t s; cudaStreamCreateWithFlags(&s, cudaStreamNonBlocking); return s;
    }();
    static cudaEvent_t evFork = [] {
        cudaEvent_t e; cudaEventCreateWithFlags(&e, cudaEventDisableTiming); return e;
    }();
    static cudaEvent_t evJoin = [] {
        cudaEvent_t e; cudaEventCreateWithFlags(&e, cudaEventDisableTiming); return e;
    }();

    cudaFuncSetAttribute(gemm_f16_kernel,
                         cudaFuncAttributeMaxDynamicSharedMemorySize, GSMEM_BYTES);
    cudaFuncSetAttribute(flash_attn_kernel,
                         cudaFuncAttributeMaxDynamicSharedMemorySize, FA_SMEM);

    const float* img_emb = (const float*)d_in[0];
    const float* txt_emb = (const float*)d_in[1];
    const float* pe      = (const float*)d_in[2];
    const float* i_asc = (const float*)d_in[3];
    const float* i_ash = (const float*)d_in[4];
    const float* i_ag  = (const float*)d_in[5];
    const float* i_msc = (const float*)d_in[6];
    const float* i_msh = (const float*)d_in[7];
    const float* i_mg  = (const float*)d_in[8];
    const float* t_asc = (const float*)d_in[9];
    const float* t_ash = (const float*)d_in[10];
    const float* t_ag  = (const float*)d_in[11];
    const float* t_msc = (const float*)d_in[12];
    const float* t_msh = (const float*)d_in[13];
    const float* t_mg  = (const float*)d_in[14];
    const float* i_qkv_w = (const float*)d_in[15];
    const float* i_qkv_b = (const float*)d_in[16];
    const float* i_qnw   = (const float*)d_in[17];
    const float* t_qkv_w = (const float*)d_in[18];
    const float* t_qkv_b = (const float*)d_in[19];
    const float* t_qnw   = (const float*)d_in[20];
    const float* proj_w  = (const float*)d_in[21];
    const float* proj_b  = (const float*)d_in[22];
    const float* i_w1 = (const float*)d_in[23];
    const float* i_b1 = (const float*)d_in[24];
    const float* i_w2 = (const float*)d_in[25];
    const float* i_b2 = (const float*)d_in[26];
    const float* t_w1 = (const float*)d_in[27];
    const float* t_b1 = (const float*)d_in[28];
    const float* t_w2 = (const float*)d_in[29];
    const float* t_b2 = (const float*)d_in[30];
    // d_in[31] = mask: all-true in this problem -> no-op in attention.

    float *p_attno, *p_xres;
    __half *p_xmod, *p_qkv, *p_ocat, *p_mlpin, *p_hid;
    __half *w_qkv_t, *w_qkv_i, *w_proj, *w_w1t, *w_w1i, *w_w2t, *w_w2i;
    cudaGetSymbolAddress((void**)&p_xmod,  g_xmod);
    cudaGetSymbolAddress((void**)&p_qkv,   g_qkv);
    cudaGetSymbolAddress((void**)&p_ocat,  g_ocat);
    cudaGetSymbolAddress((void**)&p_attno, g_attno);
    cudaGetSymbolAddress((void**)&p_xres,  g_xres);
    cudaGetSymbolAddress((void**)&p_mlpin, g_mlpin);
    cudaGetSymbolAddress((void**)&p_hid,   g_hid);
    cudaGetSymbolAddress((void**)&w_qkv_t, g_hw_qkv_t);
    cudaGetSymbolAddress((void**)&w_qkv_i, g_hw_qkv_i);
    cudaGetSymbolAddress((void**)&w_proj,  g_hw_proj);
    cudaGetSymbolAddress((void**)&w_w1t,   g_hw_w1t);
    cudaGetSymbolAddress((void**)&w_w1i,   g_hw_w1i);
    cudaGetSymbolAddress((void**)&w_w2t,   g_hw_w2t);
    cudaGetSymbolAddress((void**)&w_w2i,   g_hw_w2i);

    float* out = (float*)d_out;

    // ---- fork: proj/MLP weight conversions on side stream, hidden under the
    //      QKV+attention chain on the main (default) stream ----
    cudaEventRecord(evFork, 0);
    cudaStreamWaitEvent(s2, evFork, 0);
    f2h_on(s2, proj_w, w_proj, (long)DIMC * DIMC);
    f2h_on(s2, t_w1,   w_w1t,  (long)MLPD * DIMC);
    f2h_on(s2, i_w1,   w_w1i,  (long)MLPD * DIMC);
    f2h_on(s2, t_w2,   w_w2t,  (long)DIMC * MLPD);
    f2h_on(s2, i_w2,   w_w2i,  (long)DIMC * MLPD);
    cudaEventRecord(evJoin, s2);

    // ---- main stream: QKV chain ----
    f2h_on(0, t_qkv_w, w_qkv_t, (long)QKVD * DIMC);
    f2h_on(0, i_qkv_w, w_qkv_i, (long)QKVD * DIMC);

    // 1. LN + attn modulation -> fp16 xmod (txt rows first, then img)
    ln_mod_kernel<<<L_ALLC, 256>>>(txt_emb, img_emb, t_asc, t_ash, i_asc, i_ash);

    // 2. fused QKV GEMM (txt m-tiles 0-3, img m-tiles 4-15)
    hgemm(p_xmod, DIMC, w_qkv_t, w_qkv_i, DIMC, t_qkv_b, i_qkv_b, L_TXTC / 128,
          p_qkv, QKVD, L_ALLC, QKVD, DIMC, 2);

    // 3. RMSNorm + RoPE + scale + fp16 layout
    {
        dim3 grid(L_ALLC, NH);
        qkv_post_kernel<<<grid, DHC>>>(pe, t_qnw, i_qnw);
    }

    // 4. fused flash attention -> fp16 ocat
    {
        dim3 grid(L_ALLC / 128, NH);
        flash_attn_kernel<<<grid, 256, FA_SMEM>>>();
    }

    // ---- join: proj/MLP weights ready ----
    cudaStreamWaitEvent(0, evJoin, 0);

    // 5. shared proj (fp32 out)
    hgemm(p_ocat, DIMC, w_proj, w_proj, DIMC, proj_b, proj_b, L_ALLC / 128,
          p_attno, DIMC, L_ALLC, DIMC, DIMC, 0);

    // 6. residual + LN + mlp modulation -> fp16 mlpin (+ xres)
    res_ln_kernel<<<L_ALLC, 256>>>(txt_emb, img_emb, t_ag, i_ag, t_msc, t_msh, i_msc, i_msh);

    // 7. fused MLP up + GELU -> fp16 hid
    hgemm(p_mlpin, DIMC, w_w1t, w_w1i, DIMC, t_b1, i_b1, L_TXTC / 128,
          p_hid, MLPD, L_ALLC, MLPD, DIMC, 3);

    // 8. fused MLP down + gate + residual + output remap (img first, then txt)
    hgemm(p_hid, MLPD, w_w2t, w_w2i, MLPD, t_b2, i_b2, L_TXTC / 128,
          out, DIMC, L_ALLC, DIMC, MLPD, 4, p_xres, t_mg, i_mg);
}